// round 15
// baseline (speedup 1.0000x reference)
#include <cuda_runtime.h>
#include <cuda_bf16.h>
#include <cstdint>

#define NNODES 50000
#define NEDGES 800000
#define FEAT   128
#define DROP_SCALE 2.5f   // 1/(1-0.6)
#define NCHUNK ((NNODES + 255) / 256)   // 196

// ---------------- scratch (no allocations allowed) ----------------
__device__ float    g_bufA[NNODES * FEAT];   // z ping
__device__ float    g_bufB[NNODES * FEAT];   // z pong
__device__ int      g_deg [NNODES];
__device__ int      g_fill[NNODES];
__device__ int      g_rowptr[NNODES + 1];
__device__ int      g_col[NEDGES];
__device__ int      g_chunksum[256];
__device__ int      g_ei_is64;
__device__ int      g_mask_kind;   // 0=uint8, 1=int32, 2=float32
__device__ uint32_t g_Whi[6][128 * 64];  // pre-split weights [layer*2+half][n*64+kpair]
__device__ uint32_t g_Wlo[6][128 * 64];

// ---------------- helpers ----------------
__device__ __forceinline__ void split_pair(float x, float y, uint32_t& hi, uint32_t& lo) {
    __nv_bfloat16 hx = __float2bfloat16_rn(x);
    __nv_bfloat16 hy = __float2bfloat16_rn(y);
    float rx = x - __bfloat162float(hx);
    float ry = y - __bfloat162float(hy);
    __nv_bfloat16 lx = __float2bfloat16_rn(rx);
    __nv_bfloat16 ly = __float2bfloat16_rn(ry);
    hi = ((uint32_t)__bfloat16_as_ushort(hy) << 16) | (uint32_t)__bfloat16_as_ushort(hx);
    lo = ((uint32_t)__bfloat16_as_ushort(ly) << 16) | (uint32_t)__bfloat16_as_ushort(lx);
}

#define MMA_BF16(d, a, bv0, bv1) \
    asm volatile("mma.sync.aligned.m16n8k16.row.col.f32.bf16.bf16.f32 " \
        "{%0,%1,%2,%3}, {%4,%5,%6,%7}, {%8,%9}, {%0,%1,%2,%3};" \
        : "+f"((d)[0]), "+f"((d)[1]), "+f"((d)[2]), "+f"((d)[3]) \
        : "r"((a)[0]), "r"((a)[1]), "r"((a)[2]), "r"((a)[3]), "r"(bv0), "r"(bv1))

// Z/C pointer tags: 0 -> g_bufB, 1 -> g_bufA, else external pointer.
__device__ __forceinline__ const float* resolve_z(const float* Z) {
    if (Z == (const float*)0) return g_bufB;
    if (Z == (const float*)1) return g_bufA;
    return Z;
}
__device__ __forceinline__ float* resolve_c(float* C) {
    if (C == (float*)0) return g_bufA;
    if (C == (float*)1) return g_bufB;
    return C;
}

// ---------------- dtype probe ----------------
__global__ void probe_kernel(const int* __restrict__ ei32,
                             const unsigned int* __restrict__ mask32) {
    if (threadIdx.x != 0 || blockIdx.x != 0) return;
    int is64 = 1;
    for (int i = 1; i < 4096; i += 2) {
        if (ei32[i] != 0) { is64 = 0; break; }
    }
    g_ei_is64 = is64;
    bool allf = true, alli = true;
    for (int i = 0; i < 256; i++) {
        unsigned w = mask32[i];
        if (!(w == 0u || w == 0x3f800000u)) allf = false;
        if (!(w == 0u || w == 1u))          alli = false;
    }
    int kind = 0;
    if (alli) kind = 1;
    else if (allf) kind = 2;
    g_mask_kind = kind;
}

// ---------------- CSR build ----------------
__global__ void zero_counts_kernel() {
    int i = blockIdx.x * blockDim.x + threadIdx.x;
    if (i < NNODES) { g_deg[i] = 0; g_fill[i] = 0; }
}

__device__ __forceinline__ int load_edge(const void* ei, int pos) {
    if (g_ei_is64) return (int)((const long long*)ei)[pos];
    return ((const int*)ei)[pos];
}

__global__ void hist_kernel(const void* __restrict__ ei) {
    int e = blockIdx.x * blockDim.x + threadIdx.x;
    if (e < NEDGES) {
        int d = load_edge(ei, NEDGES + e);
        if ((unsigned)d < NNODES) atomicAdd(&g_deg[d], 1);
    }
}

__global__ void chunk_sum_kernel() {
    __shared__ int sh[256];
    int t = threadIdx.x;
    int i = blockIdx.x * 256 + t;
    int v = (i < NNODES) ? g_deg[i] : 0;
    sh[t] = v; __syncthreads();
#pragma unroll
    for (int off = 128; off > 0; off >>= 1) {
        if (t < off) sh[t] += sh[t + off];
        __syncthreads();
    }
    if (t == 0) g_chunksum[blockIdx.x] = sh[0];
}

__global__ void chunk_scan_kernel() {
    __shared__ int sh[256];
    int t = threadIdx.x;
    int v = (t < NCHUNK) ? g_chunksum[t] : 0;
    sh[t] = v; __syncthreads();
#pragma unroll
    for (int off = 1; off < 256; off <<= 1) {
        int u = (t >= off) ? sh[t - off] : 0;
        __syncthreads();
        sh[t] += u;
        __syncthreads();
    }
    g_chunksum[t] = sh[t] - v;
}

__global__ void rowptr_kernel() {
    __shared__ int sh[256];
    int t = threadIdx.x;
    int i = blockIdx.x * 256 + t;
    int v = (i < NNODES) ? g_deg[i] : 0;
    sh[t] = v; __syncthreads();
#pragma unroll
    for (int off = 1; off < 256; off <<= 1) {
        int u = (t >= off) ? sh[t - off] : 0;
        __syncthreads();
        sh[t] += u;
        __syncthreads();
    }
    int excl = sh[t] - v + g_chunksum[blockIdx.x];
    if (i < NNODES) g_rowptr[i] = excl;
    if (i == NNODES - 1) g_rowptr[NNODES] = excl + v;
}

__global__ void fill_kernel(const void* __restrict__ ei) {
    int e = blockIdx.x * blockDim.x + threadIdx.x;
    if (e < NEDGES) {
        int s = load_edge(ei, e);
        int d = load_edge(ei, NEDGES + e);
        if ((unsigned)d < NNODES && (unsigned)s < NNODES) {
            int pos = g_rowptr[d] + atomicAdd(&g_fill[d], 1);
            g_col[pos] = s;
        }
    }
}

// ---------------- layer-0 dropout (x -> g_bufB) ----------------
__global__ void dropout_kernel(const float* __restrict__ in,
                               const void* __restrict__ mask) {
    int i = blockIdx.x * blockDim.x + threadIdx.x;
    const int n4 = NNODES * FEAT / 4;
    if (i >= n4) return;
    float4 v = reinterpret_cast<const float4*>(in)[i];
    int k0, k1, k2, k3;
    int kind = g_mask_kind;
    if (kind == 0) {
        uchar4 m = reinterpret_cast<const uchar4*>(mask)[i];
        k0 = m.x; k1 = m.y; k2 = m.z; k3 = m.w;
    } else if (kind == 1) {
        int4 m = reinterpret_cast<const int4*>(mask)[i];
        k0 = m.x; k1 = m.y; k2 = m.z; k3 = m.w;
    } else {
        float4 m = reinterpret_cast<const float4*>(mask)[i];
        k0 = (m.x != 0.f); k1 = (m.y != 0.f); k2 = (m.z != 0.f); k3 = (m.w != 0.f);
    }
    float4 o;
    o.x = k0 ? v.x * DROP_SCALE : 0.0f;
    o.y = k1 ? v.y * DROP_SCALE : 0.0f;
    o.z = k2 ? v.z * DROP_SCALE : 0.0f;
    o.w = k3 ? v.w * DROP_SCALE : 0.0f;
    reinterpret_cast<float4*>(g_bufB)[i] = o;
}

// ---------------- weight pre-split: all 3 layers, one launch ----------------
__global__ void wsplit_kernel(const float* __restrict__ Wr0, const float* __restrict__ Wt0,
                              const float* __restrict__ Wr1, const float* __restrict__ Wt1,
                              const float* __restrict__ Wr2, const float* __restrict__ Wt2) {
    int i = blockIdx.x * blockDim.x + threadIdx.x;
    if (i >= 128 * 64) return;
    const float* Ws[6] = {Wr0, Wt0, Wr1, Wt1, Wr2, Wt2};
#pragma unroll
    for (int l = 0; l < 6; l++) {
        float2 a = *reinterpret_cast<const float2*>(Ws[l] + 2 * i);
        split_pair(a.x, a.y, g_Whi[l][i], g_Wlo[l][i]);
    }
}

// ================= fused gather + mma.sync bf16 dual GEMM =================
// Phase 1: gather-aggregate 4 agg K-chunks over CSR into resident smem
//          (fp32 reg accumulate -> bf16 hi/lo split). No MMA regs live.
// Phase 2: 8-chunk MMA loop; agg chunks from resident smem, root chunks
//          loaded per-chunk from Z. 3 bf16 products, fp32 acc.
// Epilogue: bias + relu + next-layer dropout -> C (never in place: other
//          CTAs still gather from Z).
__global__ __launch_bounds__(256, 2) void gemm_fused_kernel(
    const float* Ztag, int layer,
    const float* __restrict__ bias,
    const void*  __restrict__ nextMask,
    float* Ctag, int doRelu) {
    extern __shared__ uint32_t dsm[];
    uint32_t* sAggHi = dsm;             // [4][2048]
    uint32_t* sAggLo = dsm + 8192;
    uint32_t* sAh    = dsm + 16384;
    uint32_t* sAl    = dsm + 18432;
    uint32_t* sBh    = dsm + 20480;
    uint32_t* sBl    = dsm + 22528;

    const float* Z = resolve_z(Ztag);
    float*       C = resolve_c(Ctag);

    const int tid  = threadIdx.x;
    const int warp = tid >> 5;
    const int lane = tid & 31;
    const int wm   = warp & 3;
    const int wn   = warp >> 2;
    const int row0 = blockIdx.x * 128;

    // ---------------- phase 1: gather agg chunks ----------------
    {
        const int r  = tid >> 1;
        const int t  = tid & 1;
        const int gr = row0 + r;
        int beg = 0, end = 0;
        if (gr < NNODES) { beg = g_rowptr[gr]; end = g_rowptr[gr + 1]; }
        const int sw = (r & 3) << 2;

        for (int c = 0; c < 4; c++) {
            float acc[16];
#pragma unroll
            for (int i = 0; i < 16; i++) acc[i] = 0.f;
            const float* zb = Z + c * 32 + t * 16;
            int e = beg;
            for (; e + 2 <= end; e += 2) {
                int s0 = __ldg(&g_col[e]);
                int s1 = __ldg(&g_col[e + 1]);
                const float4* p0 = reinterpret_cast<const float4*>(zb + (size_t)s0 * FEAT);
                const float4* p1 = reinterpret_cast<const float4*>(zb + (size_t)s1 * FEAT);
                float4 a0 = __ldg(p0 + 0), a1 = __ldg(p0 + 1), a2 = __ldg(p0 + 2), a3 = __ldg(p0 + 3);
                float4 b0 = __ldg(p1 + 0), b1 = __ldg(p1 + 1), b2 = __ldg(p1 + 2), b3 = __ldg(p1 + 3);
                acc[0]  += a0.x + b0.x; acc[1]  += a0.y + b0.y; acc[2]  += a0.z + b0.z; acc[3]  += a0.w + b0.w;
                acc[4]  += a1.x + b1.x; acc[5]  += a1.y + b1.y; acc[6]  += a1.z + b1.z; acc[7]  += a1.w + b1.w;
                acc[8]  += a2.x + b2.x; acc[9]  += a2.y + b2.y; acc[10] += a2.z + b2.z; acc[11] += a2.w + b2.w;
                acc[12] += a3.x + b3.x; acc[13] += a3.y + b3.y; acc[14] += a3.z + b3.z; acc[15] += a3.w + b3.w;
            }
            if (e < end) {
                int s0 = __ldg(&g_col[e]);
                const float4* p0 = reinterpret_cast<const float4*>(zb + (size_t)s0 * FEAT);
                float4 a0 = __ldg(p0 + 0), a1 = __ldg(p0 + 1), a2 = __ldg(p0 + 2), a3 = __ldg(p0 + 3);
                acc[0]  += a0.x; acc[1]  += a0.y; acc[2]  += a0.z; acc[3]  += a0.w;
                acc[4]  += a1.x; acc[5]  += a1.y; acc[6]  += a1.z; acc[7]  += a1.w;
                acc[8]  += a2.x; acc[9]  += a2.y; acc[10] += a2.z; acc[11] += a2.w;
                acc[12] += a3.x; acc[13] += a3.y; acc[14] += a3.z; acc[15] += a3.w;
            }
            uint32_t ph[8], pl[8];
#pragma unroll
            for (int j = 0; j < 8; j++) split_pair(acc[2 * j], acc[2 * j + 1], ph[j], pl[j]);
            uint32_t* hB = sAggHi + c * 2048;
            uint32_t* lB = sAggLo + c * 2048;
            int w0 = r * 16 + ((8 * t + 0) ^ sw);
            int w1 = r * 16 + ((8 * t + 4) ^ sw);
            *reinterpret_cast<uint4*>(&hB[w0]) = make_uint4(ph[0], ph[4], ph[1], ph[5]);
            *reinterpret_cast<uint4*>(&lB[w0]) = make_uint4(pl[0], pl[4], pl[1], pl[5]);
            *reinterpret_cast<uint4*>(&hB[w1]) = make_uint4(ph[2], ph[6], ph[3], ph[7]);
            *reinterpret_cast<uint4*>(&lB[w1]) = make_uint4(pl[2], pl[6], pl[3], pl[7]);
        }
    }
    __syncthreads();

    // ---------------- phase 2: MMA loop ----------------
    float acc[2][8][4];
#pragma unroll
    for (int a = 0; a < 2; a++)
#pragma unroll
        for (int b = 0; b < 8; b++)
#pragma unroll
            for (int c = 0; c < 4; c++) acc[a][b][c] = 0.f;

    for (int ch = 0; ch < 8; ch++) {
        const uint32_t* Whp = g_Whi[layer * 2 + ((ch < 4) ? 0 : 1)];
        const uint32_t* Wlp = g_Wlo[layer * 2 + ((ch < 4) ? 0 : 1)];
        const int k0  = (ch & 3) * 32;
        const int kp0 = (ch & 3) * 16;

        if (ch >= 4) {
            const int r  = tid >> 1;
            const int t  = tid & 1;
            const int gr = row0 + r;
            const int sw = (r & 3) << 2;
            float4 a0, a1, a2, a3;
            a0 = a1 = a2 = a3 = make_float4(0.f, 0.f, 0.f, 0.f);
            if (gr < NNODES) {
                const float4* p = reinterpret_cast<const float4*>(Z + (size_t)gr * FEAT + k0 + t * 16);
                a0 = p[0]; a1 = p[1]; a2 = p[2]; a3 = p[3];
            }
            float f[16] = {a0.x, a0.y, a0.z, a0.w, a1.x, a1.y, a1.z, a1.w,
                           a2.x, a2.y, a2.z, a2.w, a3.x, a3.y, a3.z, a3.w};
            uint32_t ph[8], pl[8];
#pragma unroll
            for (int j = 0; j < 8; j++) split_pair(f[2 * j], f[2 * j + 1], ph[j], pl[j]);
            int w0 = r * 16 + ((8 * t + 0) ^ sw);
            int w1 = r * 16 + ((8 * t + 4) ^ sw);
            *reinterpret_cast<uint4*>(&sAh[w0]) = make_uint4(ph[0], ph[4], ph[1], ph[5]);
            *reinterpret_cast<uint4*>(&sAl[w0]) = make_uint4(pl[0], pl[4], pl[1], pl[5]);
            *reinterpret_cast<uint4*>(&sAh[w1]) = make_uint4(ph[2], ph[6], ph[3], ph[7]);
            *reinterpret_cast<uint4*>(&sAl[w1]) = make_uint4(pl[2], pl[6], pl[3], pl[7]);
        }

#pragma unroll
        for (int jj = 0; jj < 2; jj++) {
            int u = tid + 256 * jj;
            int n = u >> 2, g = (u >> 1) & 1, h = u & 1;
            int kp = kp0 + g * 8 + 2 * h;
            const uint32_t* sh_ = Whp + n * 64 + kp;
            const uint32_t* sl_ = Wlp + n * 64 + kp;
            uint2 hA = *reinterpret_cast<const uint2*>(sh_);
            uint2 hB = *reinterpret_cast<const uint2*>(sh_ + 4);
            uint2 lA = *reinterpret_cast<const uint2*>(sl_);
            uint2 lB = *reinterpret_cast<const uint2*>(sl_ + 4);
            int waddr = n * 16 + ((g * 8 + 4 * h) ^ ((n & 3) << 2));
            *reinterpret_cast<uint4*>(&sBh[waddr]) = make_uint4(hA.x, hB.x, hA.y, hB.y);
            *reinterpret_cast<uint4*>(&sBl[waddr]) = make_uint4(lA.x, lB.x, lA.y, lB.y);
        }
        __syncthreads();

        const uint32_t* aH = (ch < 4) ? (sAggHi + ch * 2048) : sAh;
        const uint32_t* aL = (ch < 4) ? (sAggLo + ch * 2048) : sAl;

#pragma unroll
        for (int ks = 0; ks < 2; ks++) {
            const int q = ks * 8 + 2 * (lane & 3);
            uint32_t Ah[2][4], Al[2][4];
#pragma unroll
            for (int mt = 0; mt < 2; mt++) {
                int r = wm * 32 + mt * 16 + (lane >> 2);
                int w0 = r * 16 + (q ^ ((r & 3) << 2));
                int w1 = w0 + 8 * 16;
                uint2 t0 = *reinterpret_cast<const uint2*>(&aH[w0]);
                uint2 t1 = *reinterpret_cast<const uint2*>(&aH[w1]);
                Ah[mt][0] = t0.x; Ah[mt][1] = t1.x; Ah[mt][2] = t0.y; Ah[mt][3] = t1.y;
                uint2 u0 = *reinterpret_cast<const uint2*>(&aL[w0]);
                uint2 u1 = *reinterpret_cast<const uint2*>(&aL[w1]);
                Al[mt][0] = u0.x; Al[mt][1] = u1.x; Al[mt][2] = u0.y; Al[mt][3] = u1.y;
            }
#pragma unroll
            for (int nt = 0; nt < 8; nt++) {
                int n = wn * 64 + nt * 8 + (lane >> 2);
                int w = n * 16 + (q ^ ((n & 3) << 2));
                uint2 bh = *reinterpret_cast<const uint2*>(&sBh[w]);
                uint2 bl = *reinterpret_cast<const uint2*>(&sBl[w]);
#pragma unroll
                for (int mt = 0; mt < 2; mt++) {
                    MMA_BF16(acc[mt][nt], Ah[mt], bh.x, bh.y);
                    MMA_BF16(acc[mt][nt], Al[mt], bh.x, bh.y);
                    MMA_BF16(acc[mt][nt], Ah[mt], bl.x, bl.y);
                }
            }
        }
        __syncthreads();
    }

    // ---- epilogue ----
    const int kind = g_mask_kind;
    float2 biasv[8];
#pragma unroll
    for (int nt = 0; nt < 8; nt++) {
        int col = wn * 64 + nt * 8 + 2 * (lane & 3);
        biasv[nt] = *reinterpret_cast<const float2*>(bias + col);
    }

#pragma unroll
    for (int mt = 0; mt < 2; mt++) {
        int rbase = row0 + wm * 32 + mt * 16 + (lane >> 2);
#pragma unroll
        for (int half = 0; half < 2; half++) {
            int row = rbase + 8 * half;
            if (row >= NNODES) continue;
#pragma unroll
            for (int nt = 0; nt < 8; nt++) {
                int col = wn * 64 + nt * 8 + 2 * (lane & 3);
                float v0 = acc[mt][nt][2 * half + 0] + biasv[nt].x;
                float v1 = acc[mt][nt][2 * half + 1] + biasv[nt].y;
                if (doRelu) { v0 = fmaxf(v0, 0.f); v1 = fmaxf(v1, 0.f); }
                if (nextMask) {
                    size_t ib = (size_t)row * FEAT + col;
                    int m0, m1;
                    if (kind == 0) {
                        const unsigned char* m = (const unsigned char*)nextMask;
                        m0 = m[ib]; m1 = m[ib + 1];
                    } else if (kind == 1) {
                        const int* m = (const int*)nextMask;
                        m0 = m[ib]; m1 = m[ib + 1];
                    } else {
                        const float* m = (const float*)nextMask;
                        m0 = (m[ib] != 0.f); m1 = (m[ib + 1] != 0.f);
                    }
                    v0 = m0 ? v0 * DROP_SCALE : 0.f;
                    v1 = m1 ? v1 * DROP_SCALE : 0.f;
                }
                *reinterpret_cast<float2*>(C + (size_t)row * FEAT + col) = make_float2(v0, v1);
            }
        }
    }
}

// ---------------- launch (graph-capture safe) --------
extern "C" void kernel_launch(void* const* d_in, const int* in_sizes, int n_in,
                              void* d_out, int out_size) {
    const float* x      = (const float*)d_in[0];
    const void*  ei     = d_in[1];
    const float* Wrel0  = (const float*)d_in[2];
    const float* Wroot0 = (const float*)d_in[3];
    const float* b0     = (const float*)d_in[4];
    const float* Wrel1  = (const float*)d_in[5];
    const float* Wroot1 = (const float*)d_in[6];
    const float* b1     = (const float*)d_in[7];
    const float* Wrel2  = (const float*)d_in[8];
    const float* Wroot2 = (const float*)d_in[9];
    const float* b2     = (const float*)d_in[10];
    const void*  drop0  = d_in[11];
    const void*  drop1  = d_in[12];
    const void*  drop2  = d_in[13];

    float* out = (float*)d_out;

    const int TB = 256;
    const int nodeBlocks = (NNODES + TB - 1) / TB;
    const int edgeBlocks = (NEDGES + TB - 1) / TB;
    const int elemBlocks = (NNODES * FEAT / 4 + TB - 1) / TB;
    const int gemmBlocks = (NNODES + 127) / 128;
    const int wsplitBlocks = (128 * 64 + TB - 1) / TB;
    const int FUSED_SMEM = 24576 * 4;    // 96KB

    cudaFuncSetAttribute(gemm_fused_kernel,
                         cudaFuncAttributeMaxDynamicSharedMemorySize, FUSED_SMEM);

    probe_kernel<<<1, 32>>>((const int*)ei, (const unsigned int*)drop0);

    // CSR build
    zero_counts_kernel<<<nodeBlocks, TB>>>();
    hist_kernel<<<edgeBlocks, TB>>>(ei);
    chunk_sum_kernel<<<NCHUNK, 256>>>();
    chunk_scan_kernel<<<1, 256>>>();
    rowptr_kernel<<<NCHUNK, 256>>>();
    fill_kernel<<<edgeBlocks, TB>>>(ei);

    wsplit_kernel<<<wsplitBlocks, TB>>>(Wrel0, Wroot0, Wrel1, Wroot1, Wrel2, Wroot2);
    dropout_kernel<<<elemBlocks, TB>>>(x, drop0);   // x -> g_bufB

    // layer 0: Z = g_bufB (tag 0), C = g_bufA (tag 0)
    gemm_fused_kernel<<<gemmBlocks, 256, FUSED_SMEM>>>((const float*)0, 0, b0, drop1, (float*)0, 1);
    // layer 1: Z = g_bufA (tag 1), C = g_bufB (tag 1)
    gemm_fused_kernel<<<gemmBlocks, 256, FUSED_SMEM>>>((const float*)1, 1, b1, drop2, (float*)1, 1);
    // layer 2: Z = g_bufB (tag 0), C = out (external)
    gemm_fused_kernel<<<gemmBlocks, 256, FUSED_SMEM>>>((const float*)0, 2, b2, nullptr, out, 0);
}